// round 1
// baseline (speedup 1.0000x reference)
#include <cuda_runtime.h>
#include <cuda_bf16.h>

// out[s, :] = W_tok[x[s], :] + b_tok + W_pos[(S-1)-s, :] + b_pos
// Inputs (metadata order): x[int32, S], W_tok[f32, V*D], b_tok[f32, D],
//                          W_pos[f32, MAX_CTX*D], b_pos[f32, D]
// Output: f32 [S, D], S=8192, D=1024.

#define EMBED 1024
#define VEC   (EMBED / 4)   // 256 float4 per row

__global__ __launch_bounds__(256)
void embed_kernel(const int* __restrict__ x,
                  const float4* __restrict__ W_tok,
                  const float4* __restrict__ b_tok,
                  const float4* __restrict__ W_pos,
                  const float4* __restrict__ b_pos,
                  float4* __restrict__ out,
                  int S)
{
    int s = blockIdx.x;
    if (s >= S) return;
    int tok = x[s];              // broadcast load, L1-hit for all threads
    int pos = (S - 1) - s;

    const float4* trow = W_tok + (size_t)tok * VEC;
    const float4* prow = W_pos + (size_t)pos * VEC;
    float4*       orow = out   + (size_t)s   * VEC;

    int d = threadIdx.x;         // 256 threads, one float4 each
    float4 t = trow[d];
    float4 p = prow[d];
    float4 bt = b_tok[d];
    float4 bp = b_pos[d];
    float4 r;
    r.x = t.x + bt.x + p.x + bp.x;
    r.y = t.y + bt.y + p.y + bp.y;
    r.z = t.z + bt.z + p.z + bp.z;
    r.w = t.w + bt.w + p.w + bp.w;
    orow[d] = r;
}

extern "C" void kernel_launch(void* const* d_in, const int* in_sizes, int n_in,
                              void* d_out, int out_size)
{
    const int*    x     = (const int*)   d_in[0];
    const float4* W_tok = (const float4*)d_in[1];
    const float4* b_tok = (const float4*)d_in[2];
    const float4* W_pos = (const float4*)d_in[3];
    const float4* b_pos = (const float4*)d_in[4];
    float4*       out   = (float4*)d_out;

    int S = in_sizes[0];         // 8192
    embed_kernel<<<S, 256>>>(x, W_tok, b_tok, W_pos, b_pos, out, S);
}

// round 2
// speedup vs baseline: 1.0628x; 1.0628x over previous
#include <cuda_runtime.h>
#include <cuda_bf16.h>

// out[s, :] = W_tok[x[s], :] + b_tok + W_pos[(S-1)-s, :] + b_pos
// Inputs: x[int32, S], W_tok[f32, V*D], b_tok[f32, D], W_pos[f32, MAX_CTX*D], b_pos[f32, D]
// Output: f32 [S, D], S=8192, D=1024.

#define EMBED 1024
#define VEC   (EMBED / 4)   // 256 float4 per row
#define ROWS  4             // rows per CTA -> 8 independent DRAM loads in flight/thread

__global__ __launch_bounds__(256)
void embed_kernel(const int* __restrict__ x,
                  const float4* __restrict__ W_tok,
                  const float4* __restrict__ b_tok,
                  const float4* __restrict__ W_pos,
                  const float4* __restrict__ b_pos,
                  float4* __restrict__ out,
                  int S)
{
    const int base = blockIdx.x * ROWS;
    const int d = threadIdx.x;

    // Bias sum: loaded once per thread (L1-resident), reused for all rows.
    float4 bt = b_tok[d];
    float4 bp = b_pos[d];
    float4 bs;
    bs.x = bt.x + bp.x;  bs.y = bt.y + bp.y;
    bs.z = bt.z + bp.z;  bs.w = bt.w + bp.w;

    // Front-batch the index loads (broadcast, L1-hit).
    int toks[ROWS];
#pragma unroll
    for (int r = 0; r < ROWS; r++) toks[r] = x[base + r];

    // Front-batch all DRAM loads: 4 gathered token rows + 4 streaming pos rows
    // = 8 outstanding LDG.128 per thread before any dependency.
    float4 t[ROWS], p[ROWS];
#pragma unroll
    for (int r = 0; r < ROWS; r++)
        t[r] = W_tok[(size_t)toks[r] * VEC + d];
#pragma unroll
    for (int r = 0; r < ROWS; r++)
        p[r] = W_pos[(size_t)((S - 1) - (base + r)) * VEC + d];

#pragma unroll
    for (int r = 0; r < ROWS; r++) {
        float4 o;
        o.x = t[r].x + p[r].x + bs.x;
        o.y = t[r].y + p[r].y + bs.y;
        o.z = t[r].z + p[r].z + bs.z;
        o.w = t[r].w + p[r].w + bs.w;
        out[(size_t)(base + r) * VEC + d] = o;
    }
}

extern "C" void kernel_launch(void* const* d_in, const int* in_sizes, int n_in,
                              void* d_out, int out_size)
{
    const int*    x     = (const int*)   d_in[0];
    const float4* W_tok = (const float4*)d_in[1];
    const float4* b_tok = (const float4*)d_in[2];
    const float4* W_pos = (const float4*)d_in[3];
    const float4* b_pos = (const float4*)d_in[4];
    float4*       out   = (float4*)d_out;

    int S = in_sizes[0];                 // 8192
    embed_kernel<<<S / ROWS, 256>>>(x, W_tok, b_tok, W_pos, b_pos, out, S);
}